// round 4
// baseline (speedup 1.0000x reference)
#include <cuda_runtime.h>

#define NPTS   16384
#define NPOINT 4096
#define BATCH  2
#define NSAMP  32
#define CIN    64

#define OUT_XYZ   0
#define OUT_FEAT  (BATCH*NPOINT*3)                 /* 24576 */
#define OUT_SAMP  (OUT_FEAT + BATCH*128*NPOINT)    /* 1073152 */

__device__ float g_featsT[BATCH*NPTS*CIN];   // features transposed to [B,N,C]
__device__ int   g_idx[BATCH*NPOINT*NSAMP];  // ball query result

#define FMA2(acc, a, b) asm("fma.rn.f32x2 %0, %1, %2, %0;" : "+l"(acc) : "l"(a), "l"(b))
#define BCAST2(dst, f)  asm("mov.b64 %0, {%1, %1};" : "=l"(dst) : "r"(__float_as_uint(f)))
#define UNPK2(lo, hi, v) asm("mov.b64 {%0, %1}, %2;" : "=f"(lo), "=f"(hi) : "l"(v))

// ---------------------------------------------------------------------------
// K0: fused transpose (blocks [0,2048)) + ball query (blocks [2048,3072)).
// Independent work overlapped in one launch.
// ---------------------------------------------------------------------------
#define TRANS_BLOCKS 2048
__global__ void __launch_bounds__(256) k_pre(const float* __restrict__ f,
                                             const float* __restrict__ xyz,
                                             float* __restrict__ out) {
    int bid = blockIdx.x;
    if (bid < TRANS_BLOCKS) {
        // ---- transpose features [B,C,N] -> g_featsT [B,N,C] ----
        __shared__ float tile[32][33];
        int nBase = (bid & 511) * 32;
        int cBase = ((bid >> 9) & 1) * 32;
        int b = bid >> 10;
        const float* src = f + (size_t)b * CIN * NPTS;
        float* dst = g_featsT + (size_t)b * NPTS * CIN;
        int tx = threadIdx.x & 31, ty = threadIdx.x >> 5;  // 32 x 8
        #pragma unroll
        for (int i = 0; i < 32; i += 8)
            tile[ty + i][tx] = src[(size_t)(cBase + ty + i) * NPTS + nBase + tx];
        __syncthreads();
        #pragma unroll
        for (int i = 0; i < 32; i += 8)
            dst[(size_t)(nBase + ty + i) * CIN + cBase + tx] = tile[tx][ty + i];
    } else {
        // ---- ball query, warp per centroid ----
        const float R2C = (float)(0.4 * 0.4);
        int warp = (bid - TRANS_BLOCKS) * 8 + (threadIdx.x >> 5);
        int lane = threadIdx.x & 31;
        int b = warp / NPOINT, s = warp - b * NPOINT;
        const float* X = xyz + (size_t)b * NPTS * 3;
        float cx = X[s * 3 + 0], cy = X[s * 3 + 1], cz = X[s * 3 + 2];
        float cc = __fadd_rn(__fadd_rn(__fmul_rn(cx, cx), __fmul_rn(cy, cy)), __fmul_rn(cz, cz));

        int cnt = 0, first = 0;
        bool haveFirst = false;
        int* ibase = g_idx + (size_t)warp * NSAMP;

        for (int n0 = 0; n0 < NPTS && cnt < NSAMP; n0 += 32) {
            int n = n0 + lane;
            float px = X[n * 3 + 0], py = X[n * 3 + 1], pz = X[n * 3 + 2];
            float pp = __fadd_rn(__fadd_rn(__fmul_rn(px, px), __fmul_rn(py, py)), __fmul_rn(pz, pz));
            float dt = __fadd_rn(__fadd_rn(__fmul_rn(cx, px), __fmul_rn(cy, py)), __fmul_rn(cz, pz));
            float d2 = __fsub_rn(__fadd_rn(cc, pp), __fmul_rn(2.0f, dt));
            bool pred = d2 < R2C;
            unsigned m = __ballot_sync(0xffffffffu, pred);
            if (m) {
                if (!haveFirst) { first = n0 + __ffs(m) - 1; haveFirst = true; }
                if (pred) {
                    int rank = cnt + __popc(m & ((1u << lane) - 1u));
                    if (rank < NSAMP) ibase[rank] = n;
                }
                cnt += __popc(m);
                if (cnt > NSAMP) cnt = NSAMP;
            }
        }
        if (lane >= cnt) ibase[lane] = first;

        if (lane == 0) {
            float* o = out + OUT_XYZ + (size_t)(b * NPOINT + s) * 3;
            o[0] = cx; o[1] = cy; o[2] = cz;
            out[OUT_SAMP + b * NPOINT + s] = (float)s;
        }
    }
}

// ---------------------------------------------------------------------------
// K1: fused gather + 3-layer MLP (packed f32x2 FMA) + max-pool.
// 128 threads, 2 centroids (64 rows) per CTA.
// ---------------------------------------------------------------------------
#define LDA 69
#define LDB 65
#define LDC 129
#define OFF_W1 0
#define OFF_B1 4288
#define OFF_W2 4352
#define OFF_B2 8448
#define OFF_W3 8512
#define OFF_B3 16704
#define OFF_A  16832   /* 64*69 = 4416 floats */
#define OFF_Bb 21248   /* 64*65 = 4160 floats */
#define SMEM_FLOATS 25408

__global__ void __launch_bounds__(128, 2) k_mlp(
    const float* __restrict__ xyz,
    const float* __restrict__ W1, const float* __restrict__ b1,
    const float* __restrict__ W2, const float* __restrict__ b2,
    const float* __restrict__ W3, const float* __restrict__ b3,
    float* __restrict__ out)
{
    extern __shared__ float sm[];
    const int tid = threadIdx.x;

    for (int i = tid; i < 4288; i += 128) sm[OFF_W1 + i] = W1[i];
    for (int i = tid; i < 4096; i += 128) sm[OFF_W2 + i] = W2[i];
    for (int i = tid; i < 8192; i += 128) sm[OFF_W3 + i] = W3[i];
    if (tid < 64)  { sm[OFF_B1 + tid] = b1[tid]; sm[OFF_B2 + tid] = b2[tid]; }
    sm[OFF_B3 + tid] = b3[tid];

    const int cta = blockIdx.x;         // 0..4095
    const int b = cta >> 11;
    const int s0 = (cta & 2047) * 2;    // 2 centroids per CTA
    const float* X = xyz + (size_t)b * NPTS * 3;
    const float* F = g_featsT + (size_t)b * NPTS * CIN;

    // gather: 64 rows x 67 cols into Abuf. 2 threads per row.
    {
        int r = tid >> 1, half = tid & 1;
        int s = s0 + (r >> 5);
        int k = r & 31;
        int n = g_idx[((size_t)(b * NPOINT + s)) * NSAMP + k];
        float* arow = sm + OFF_A + r * LDA;
        if (half == 0) {
            arow[0] = X[n * 3 + 0] - X[s * 3 + 0];
            arow[1] = X[n * 3 + 1] - X[s * 3 + 1];
            arow[2] = X[n * 3 + 2] - X[s * 3 + 2];
            const float4* fr = (const float4*)(F + (size_t)n * CIN);
            #pragma unroll
            for (int q = 0; q < 8; q++) {
                float4 v = fr[q];
                arow[3 + 4 * q] = v.x; arow[4 + 4 * q] = v.y;
                arow[5 + 4 * q] = v.z; arow[6 + 4 * q] = v.w;
            }
        } else {
            const float4* fr = (const float4*)(F + (size_t)n * CIN + 32);
            #pragma unroll
            for (int q = 0; q < 8; q++) {
                float4 v = fr[q];
                arow[35 + 4 * q] = v.x; arow[36 + 4 * q] = v.y;
                arow[37 + 4 * q] = v.z; arow[38 + 4 * q] = v.w;
            }
        }
    }
    __syncthreads();

    // layers 1/2: 8 colgroups (8 cols) x 16 rowgroups (4 rows)
    const int tx = tid & 7, ty = tid >> 3;
    const int r0 = ty * 4;
    float* Abuf = sm + OFF_A;
    float* Bbuf = sm + OFF_Bb;

    // ---- layer 1: relu(A[64x67] @ W1[67x64] + b1) -> Bbuf ----
    {
        unsigned long long acc[4][4];
        #pragma unroll
        for (int i = 0; i < 4; i++)
            #pragma unroll
            for (int j = 0; j < 4; j++) acc[i][j] = 0ull;
        const float* wp = sm + OFF_W1 + tx * 8;
        #pragma unroll 4
        for (int k = 0; k < 67; k++) {
            ulonglong2 wA = *(const ulonglong2*)(wp + k * 64);
            ulonglong2 wB = *(const ulonglong2*)(wp + k * 64 + 4);
            #pragma unroll
            for (int i = 0; i < 4; i++) {
                unsigned long long aa;
                BCAST2(aa, Abuf[(r0 + i) * LDA + k]);
                FMA2(acc[i][0], aa, wA.x); FMA2(acc[i][1], aa, wA.y);
                FMA2(acc[i][2], aa, wB.x); FMA2(acc[i][3], aa, wB.y);
            }
        }
        const float* bp = sm + OFF_B1 + tx * 8;
        #pragma unroll
        for (int i = 0; i < 4; i++) {
            float* o = Bbuf + (r0 + i) * LDB + tx * 8;
            #pragma unroll
            for (int j = 0; j < 4; j++) {
                float lo, hi; UNPK2(lo, hi, acc[i][j]);
                o[2 * j]     = fmaxf(lo + bp[2 * j], 0.f);
                o[2 * j + 1] = fmaxf(hi + bp[2 * j + 1], 0.f);
            }
        }
    }
    __syncthreads();

    // ---- layer 2: relu(Bbuf[64x64] @ W2[64x64] + b2) -> Abuf ----
    {
        unsigned long long acc[4][4];
        #pragma unroll
        for (int i = 0; i < 4; i++)
            #pragma unroll
            for (int j = 0; j < 4; j++) acc[i][j] = 0ull;
        const float* wp = sm + OFF_W2 + tx * 8;
        #pragma unroll 4
        for (int k = 0; k < 64; k++) {
            ulonglong2 wA = *(const ulonglong2*)(wp + k * 64);
            ulonglong2 wB = *(const ulonglong2*)(wp + k * 64 + 4);
            #pragma unroll
            for (int i = 0; i < 4; i++) {
                unsigned long long aa;
                BCAST2(aa, Bbuf[(r0 + i) * LDB + k]);
                FMA2(acc[i][0], aa, wA.x); FMA2(acc[i][1], aa, wA.y);
                FMA2(acc[i][2], aa, wB.x); FMA2(acc[i][3], aa, wB.y);
            }
        }
        const float* bp = sm + OFF_B2 + tx * 8;
        #pragma unroll
        for (int i = 0; i < 4; i++) {
            float* o = Abuf + (r0 + i) * LDA + tx * 8;
            #pragma unroll
            for (int j = 0; j < 4; j++) {
                float lo, hi; UNPK2(lo, hi, acc[i][j]);
                o[2 * j]     = fmaxf(lo + bp[2 * j], 0.f);
                o[2 * j + 1] = fmaxf(hi + bp[2 * j + 1], 0.f);
            }
        }
    }
    __syncthreads();

    // ---- layer 3: relu(Abuf[64x64] @ W3[64x128] + b3): 8 colgroups x 16 cols ----
    unsigned long long acc3[4][8];
    #pragma unroll
    for (int i = 0; i < 4; i++)
        #pragma unroll
        for (int j = 0; j < 8; j++) acc3[i][j] = 0ull;
    {
        const float* wp = sm + OFF_W3 + tx * 16;
        #pragma unroll 2
        for (int k = 0; k < 64; k++) {
            ulonglong2 w0 = *(const ulonglong2*)(wp + k * 128);
            ulonglong2 w1 = *(const ulonglong2*)(wp + k * 128 + 4);
            ulonglong2 w2 = *(const ulonglong2*)(wp + k * 128 + 8);
            ulonglong2 w3 = *(const ulonglong2*)(wp + k * 128 + 12);
            #pragma unroll
            for (int i = 0; i < 4; i++) {
                unsigned long long aa;
                BCAST2(aa, Abuf[(r0 + i) * LDA + k]);
                FMA2(acc3[i][0], aa, w0.x); FMA2(acc3[i][1], aa, w0.y);
                FMA2(acc3[i][2], aa, w1.x); FMA2(acc3[i][3], aa, w1.y);
                FMA2(acc3[i][4], aa, w2.x); FMA2(acc3[i][5], aa, w2.y);
                FMA2(acc3[i][6], aa, w3.x); FMA2(acc3[i][7], aa, w3.y);
            }
        }
    }
    __syncthreads();  // done reading Abuf before overwriting region with H3

    {
        const float* bp = sm + OFF_B3 + tx * 16;
        #pragma unroll
        for (int i = 0; i < 4; i++) {
            float* o = sm + OFF_A + (r0 + i) * LDC + tx * 16;
            #pragma unroll
            for (int j = 0; j < 8; j++) {
                float lo, hi; UNPK2(lo, hi, acc3[i][j]);
                o[2 * j]     = fmaxf(lo + bp[2 * j], 0.f);
                o[2 * j + 1] = fmaxf(hi + bp[2 * j + 1], 0.f);
            }
        }
    }
    __syncthreads();

    // ---- max over 32 samples per centroid; write out[b][c][s] ----
    #pragma unroll
    for (int p = tid; p < 256; p += 128) {
        int g = p >> 7, c = p & 127;
        const float* h = sm + OFF_A + (g * 32) * LDC + c;
        float mx = h[0];
        #pragma unroll
        for (int kk = 1; kk < 32; kk++) mx = fmaxf(mx, h[kk * LDC]);
        out[OUT_FEAT + ((size_t)(b * 128 + c)) * NPOINT + (s0 + g)] = mx;
    }
}

// ---------------------------------------------------------------------------
extern "C" void kernel_launch(void* const* d_in, const int* in_sizes, int n_in,
                              void* d_out, int out_size) {
    const float* xyz      = (const float*)d_in[0];
    const float* features = (const float*)d_in[1];
    const float* W1 = (const float*)d_in[2];
    const float* b1 = (const float*)d_in[3];
    const float* W2 = (const float*)d_in[4];
    const float* b2 = (const float*)d_in[5];
    const float* W3 = (const float*)d_in[6];
    const float* b3 = (const float*)d_in[7];
    float* out = (float*)d_out;
    (void)in_sizes; (void)n_in; (void)out_size;

    cudaFuncSetAttribute(k_mlp, cudaFuncAttributeMaxDynamicSharedMemorySize,
                         SMEM_FLOATS * (int)sizeof(float));

    k_pre<<<TRANS_BLOCKS + BATCH * NPOINT / 8, 256>>>(features, xyz, out);
    k_mlp<<<BATCH * NPOINT / 2, 128, SMEM_FLOATS * sizeof(float)>>>(
        xyz, W1, b1, W2, b2, W3, b3, out);
}

// round 8
// speedup vs baseline: 1.3714x; 1.3714x over previous
#include <cuda_runtime.h>

#define NPTS   16384
#define NPOINT 4096
#define BATCH  2
#define NSAMP  32
#define CIN    64

#define OUT_XYZ   0
#define OUT_FEAT  (BATCH*NPOINT*3)                 /* 24576 */
#define OUT_SAMP  (OUT_FEAT + BATCH*128*NPOINT)    /* 1073152 */

__device__ float g_featsT[BATCH*NPTS*CIN];   // features transposed to [B,N,C]
__device__ int   g_idx[BATCH*NPOINT*NSAMP];  // ball query result

// ---------------------------------------------------------------------------
// K1: transpose features [B,C,N] -> g_featsT [B,N,C]
// ---------------------------------------------------------------------------
__global__ void k_transpose(const float* __restrict__ f) {
    __shared__ float tile[32][33];
    int b = blockIdx.z;
    int nBase = blockIdx.x * 32, cBase = blockIdx.y * 32;
    const float* src = f + (size_t)b * CIN * NPTS;
    float* dst = g_featsT + (size_t)b * NPTS * CIN;
    int tx = threadIdx.x, ty = threadIdx.y;  // 32 x 8
    #pragma unroll
    for (int i = 0; i < 32; i += 8)
        tile[ty + i][tx] = src[(size_t)(cBase + ty + i) * NPTS + nBase + tx];
    __syncthreads();
    #pragma unroll
    for (int i = 0; i < 32; i += 8)
        dst[(size_t)(nBase + ty + i) * CIN + cBase + tx] = tile[tx][ty + i];
}

// ---------------------------------------------------------------------------
// K2: ball query, warp per centroid (R3 semantics, verified rel_err 0.0)
// ---------------------------------------------------------------------------
__global__ void k_ballquery(const float* __restrict__ xyz, float* __restrict__ out) {
    const float R2C = (float)(0.4 * 0.4);
    int warp = (blockIdx.x * blockDim.x + threadIdx.x) >> 5;
    int lane = threadIdx.x & 31;
    if (warp >= BATCH * NPOINT) return;
    int b = warp / NPOINT, s = warp - b * NPOINT;
    const float* X = xyz + (size_t)b * NPTS * 3;
    float cx = X[s * 3 + 0], cy = X[s * 3 + 1], cz = X[s * 3 + 2];
    float cc = __fadd_rn(__fadd_rn(__fmul_rn(cx, cx), __fmul_rn(cy, cy)), __fmul_rn(cz, cz));

    int cnt = 0, first = 0;
    bool haveFirst = false;
    int* ibase = g_idx + (size_t)warp * NSAMP;

    for (int n0 = 0; n0 < NPTS && cnt < NSAMP; n0 += 32) {
        int n = n0 + lane;
        float px = X[n * 3 + 0], py = X[n * 3 + 1], pz = X[n * 3 + 2];
        float pp = __fadd_rn(__fadd_rn(__fmul_rn(px, px), __fmul_rn(py, py)), __fmul_rn(pz, pz));
        float dt = __fadd_rn(__fadd_rn(__fmul_rn(cx, px), __fmul_rn(cy, py)), __fmul_rn(cz, pz));
        float d2 = __fsub_rn(__fadd_rn(cc, pp), __fmul_rn(2.0f, dt));
        bool pred = d2 < R2C;
        unsigned m = __ballot_sync(0xffffffffu, pred);
        if (m) {
            if (!haveFirst) { first = n0 + __ffs(m) - 1; haveFirst = true; }
            if (pred) {
                int rank = cnt + __popc(m & ((1u << lane) - 1u));
                if (rank < NSAMP) ibase[rank] = n;
            }
            cnt += __popc(m);
            if (cnt > NSAMP) cnt = NSAMP;
        }
    }
    if (lane >= cnt) ibase[lane] = first;

    if (lane == 0) {
        float* o = out + OUT_XYZ + (size_t)(b * NPOINT + s) * 3;
        o[0] = cx; o[1] = cy; o[2] = cz;
        out[OUT_SAMP + b * NPOINT + s] = (float)s;
    }
}

// ---------------------------------------------------------------------------
// K3: fused gather + MLP + max-pool. Weights via __ldg (L1/L2 resident),
// smem holds only activations -> 5 CTAs/SM. float4 k-chunks in layers 1/2.
// ---------------------------------------------------------------------------
#define LDA 68
#define LDB 68
#define LDC 132
#define OFF_A 0
#define OFF_B (64*LDA)        /* 4352 */
#define SMEM_FLOATS (64*LDA + 64*LDB)   /* 8704 floats = 34816 B */

__global__ void __launch_bounds__(128, 5) k_mlp(
    const float* __restrict__ xyz,
    const float* __restrict__ W1, const float* __restrict__ b1,
    const float* __restrict__ W2, const float* __restrict__ b2,
    const float* __restrict__ W3, const float* __restrict__ b3,
    float* __restrict__ out)
{
    extern __shared__ float sm[];
    const int tid = threadIdx.x;
    const int cta = blockIdx.x;         // 0..4095
    const int b = cta >> 11;
    const int s0 = (cta & 2047) * 2;    // 2 centroids per CTA
    const float* X = xyz + (size_t)b * NPTS * 3;
    const float* F = g_featsT + (size_t)b * NPTS * CIN;

    // gather: 64 rows x 67 cols into Abuf. 2 threads per row.
    {
        int r = tid >> 1, half = tid & 1;
        int s = s0 + (r >> 5);
        int k = r & 31;
        int n = g_idx[((size_t)(b * NPOINT + s)) * NSAMP + k];
        float* arow = sm + OFF_A + r * LDA;
        if (half == 0) {
            arow[0] = X[n * 3 + 0] - X[s * 3 + 0];
            arow[1] = X[n * 3 + 1] - X[s * 3 + 1];
            arow[2] = X[n * 3 + 2] - X[s * 3 + 2];
            const float4* fr = (const float4*)(F + (size_t)n * CIN);
            #pragma unroll
            for (int q = 0; q < 8; q++) {
                float4 v = fr[q];
                arow[3 + 4 * q] = v.x; arow[4 + 4 * q] = v.y;
                arow[5 + 4 * q] = v.z; arow[6 + 4 * q] = v.w;
            }
        } else {
            const float4* fr = (const float4*)(F + (size_t)n * CIN + 32);
            #pragma unroll
            for (int q = 0; q < 8; q++) {
                float4 v = fr[q];
                arow[35 + 4 * q] = v.x; arow[36 + 4 * q] = v.y;
                arow[37 + 4 * q] = v.z; arow[38 + 4 * q] = v.w;
            }
        }
    }
    __syncthreads();

    const int tx = tid & 15, ty = tid >> 4;   // 16 colgroups x 8 rowgroups
    float* Abuf = sm + OFF_A;
    float* Bbuf = sm + OFF_B;

    // ---- layer 1: relu(A[64x67] @ W1[67x64] + b1) -> Bbuf ----
    {
        float acc[8][4];
        #pragma unroll
        for (int i = 0; i < 8; i++) { acc[i][0]=0.f; acc[i][1]=0.f; acc[i][2]=0.f; acc[i][3]=0.f; }
        #pragma unroll 2
        for (int kc = 0; kc < 64; kc += 4) {
            float4 w0 = __ldg((const float4*)(W1 + (size_t)(kc + 0) * 64) + tx);
            float4 w1 = __ldg((const float4*)(W1 + (size_t)(kc + 1) * 64) + tx);
            float4 w2 = __ldg((const float4*)(W1 + (size_t)(kc + 2) * 64) + tx);
            float4 w3 = __ldg((const float4*)(W1 + (size_t)(kc + 3) * 64) + tx);
            #pragma unroll
            for (int i = 0; i < 8; i++) {
                float4 a = *(const float4*)(Abuf + (ty + 8 * i) * LDA + kc);
                acc[i][0] += a.x*w0.x + a.y*w1.x + a.z*w2.x + a.w*w3.x;
                acc[i][1] += a.x*w0.y + a.y*w1.y + a.z*w2.y + a.w*w3.y;
                acc[i][2] += a.x*w0.z + a.y*w1.z + a.z*w2.z + a.w*w3.z;
                acc[i][3] += a.x*w0.w + a.y*w1.w + a.z*w2.w + a.w*w3.w;
            }
        }
        #pragma unroll
        for (int k = 64; k < 67; k++) {
            float4 w = __ldg((const float4*)(W1 + (size_t)k * 64) + tx);
            #pragma unroll
            for (int i = 0; i < 8; i++) {
                float a = Abuf[(ty + 8 * i) * LDA + k];
                acc[i][0] += a*w.x; acc[i][1] += a*w.y; acc[i][2] += a*w.z; acc[i][3] += a*w.w;
            }
        }
        float4 bb = __ldg((const float4*)b1 + tx);
        #pragma unroll
        for (int i = 0; i < 8; i++) {
            float4 o;
            o.x = fmaxf(acc[i][0] + bb.x, 0.f);
            o.y = fmaxf(acc[i][1] + bb.y, 0.f);
            o.z = fmaxf(acc[i][2] + bb.z, 0.f);
            o.w = fmaxf(acc[i][3] + bb.w, 0.f);
            *(float4*)(Bbuf + (ty + 8 * i) * LDB + tx * 4) = o;
        }
    }
    __syncthreads();

    // ---- layer 2: relu(Bbuf[64x64] @ W2[64x64] + b2) -> Abuf ----
    {
        float acc[8][4];
        #pragma unroll
        for (int i = 0; i < 8; i++) { acc[i][0]=0.f; acc[i][1]=0.f; acc[i][2]=0.f; acc[i][3]=0.f; }
        #pragma unroll 2
        for (int kc = 0; kc < 64; kc += 4) {
            float4 w0 = __ldg((const float4*)(W2 + (size_t)(kc + 0) * 64) + tx);
            float4 w1 = __ldg((const float4*)(W2 + (size_t)(kc + 1) * 64) + tx);
            float4 w2 = __ldg((const float4*)(W2 + (size_t)(kc + 2) * 64) + tx);
            float4 w3 = __ldg((const float4*)(W2 + (size_t)(kc + 3) * 64) + tx);
            #pragma unroll
            for (int i = 0; i < 8; i++) {
                float4 a = *(const float4*)(Bbuf + (ty + 8 * i) * LDB + kc);
                acc[i][0] += a.x*w0.x + a.y*w1.x + a.z*w2.x + a.w*w3.x;
                acc[i][1] += a.x*w0.y + a.y*w1.y + a.z*w2.y + a.w*w3.y;
                acc[i][2] += a.x*w0.z + a.y*w1.z + a.z*w2.z + a.w*w3.z;
                acc[i][3] += a.x*w0.w + a.y*w1.w + a.z*w2.w + a.w*w3.w;
            }
        }
        float4 bb = __ldg((const float4*)b2 + tx);
        #pragma unroll
        for (int i = 0; i < 8; i++) {
            float4 o;
            o.x = fmaxf(acc[i][0] + bb.x, 0.f);
            o.y = fmaxf(acc[i][1] + bb.y, 0.f);
            o.z = fmaxf(acc[i][2] + bb.z, 0.f);
            o.w = fmaxf(acc[i][3] + bb.w, 0.f);
            *(float4*)(Abuf + (ty + 8 * i) * LDA + tx * 4) = o;
        }
    }
    __syncthreads();

    // ---- layer 3: relu(Abuf[64x64] @ W3[64x128] + b3) -> regs ----
    float acc3[8][8];
    #pragma unroll
    for (int i = 0; i < 8; i++)
        #pragma unroll
        for (int j = 0; j < 8; j++) acc3[i][j] = 0.f;
    {
        #pragma unroll 4
        for (int k = 0; k < 64; k++) {
            float4 w0 = __ldg((const float4*)(W3 + (size_t)k * 128) + tx * 2);
            float4 w1 = __ldg((const float4*)(W3 + (size_t)k * 128) + tx * 2 + 1);
            #pragma unroll
            for (int i = 0; i < 8; i++) {
                float a = Abuf[(ty + 8 * i) * LDA + k];
                acc3[i][0] += a*w0.x; acc3[i][1] += a*w0.y;
                acc3[i][2] += a*w0.z; acc3[i][3] += a*w0.w;
                acc3[i][4] += a*w1.x; acc3[i][5] += a*w1.y;
                acc3[i][6] += a*w1.z; acc3[i][7] += a*w1.w;
            }
        }
    }
    __syncthreads();  // done reading A/B before overwriting with H3 (LDC=132)

    {
        float4 bb0 = __ldg((const float4*)b3 + tx * 2);
        float4 bb1 = __ldg((const float4*)b3 + tx * 2 + 1);
        #pragma unroll
        for (int i = 0; i < 8; i++) {
            float* o = sm + (ty + 8 * i) * LDC + tx * 8;
            float4 v0, v1;
            v0.x = fmaxf(acc3[i][0] + bb0.x, 0.f);
            v0.y = fmaxf(acc3[i][1] + bb0.y, 0.f);
            v0.z = fmaxf(acc3[i][2] + bb0.z, 0.f);
            v0.w = fmaxf(acc3[i][3] + bb0.w, 0.f);
            v1.x = fmaxf(acc3[i][4] + bb1.x, 0.f);
            v1.y = fmaxf(acc3[i][5] + bb1.y, 0.f);
            v1.z = fmaxf(acc3[i][6] + bb1.z, 0.f);
            v1.w = fmaxf(acc3[i][7] + bb1.w, 0.f);
            *(float4*)(o) = v0;
            *(float4*)(o + 4) = v1;
        }
    }
    __syncthreads();

    // ---- max over 32 samples per centroid; write out[b][c][s] ----
    #pragma unroll
    for (int p = tid; p < 256; p += 128) {
        int g = p >> 7, c = p & 127;
        const float* h = sm + (g * 32) * LDC + c;
        float mx = h[0];
        #pragma unroll
        for (int kk = 1; kk < 32; kk++) mx = fmaxf(mx, h[kk * LDC]);
        out[OUT_FEAT + ((size_t)(b * 128 + c)) * NPOINT + (s0 + g)] = mx;
    }
}

// ---------------------------------------------------------------------------
extern "C" void kernel_launch(void* const* d_in, const int* in_sizes, int n_in,
                              void* d_out, int out_size) {
    const float* xyz      = (const float*)d_in[0];
    const float* features = (const float*)d_in[1];
    const float* W1 = (const float*)d_in[2];
    const float* b1 = (const float*)d_in[3];
    const float* W2 = (const float*)d_in[4];
    const float* b2 = (const float*)d_in[5];
    const float* W3 = (const float*)d_in[6];
    const float* b3 = (const float*)d_in[7];
    float* out = (float*)d_out;
    (void)in_sizes; (void)n_in; (void)out_size;

    cudaFuncSetAttribute(k_mlp, cudaFuncAttributeMaxDynamicSharedMemorySize,
                         SMEM_FLOATS * (int)sizeof(float));

    k_transpose<<<dim3(NPTS / 32, CIN / 32, BATCH), dim3(32, 8)>>>(features);
    k_ballquery<<<(BATCH * NPOINT * 32) / 256, 256>>>(xyz, out);
    k_mlp<<<BATCH * NPOINT / 2, 128, SMEM_FLOATS * sizeof(float)>>>(
        xyz, W1, b1, W2, b2, W3, b3, out);
}